// round 7
// baseline (speedup 1.0000x reference)
#include <cuda_runtime.h>
#include <cfloat>
#include <cstdint>

// Problem constants (fixed by reference: HIDDEN=128, NUM_HEADS=8)
constexpr int DH   = 16;
constexpr int NH   = 8;
constexpr int HID  = 128;
constexpr int TPB  = 128;   // 4 warps
constexpr int QW   = 16;    // queries per warp (mma M)
constexpr int QBLK = 64;    // queries per block
constexpr int TK   = 128;   // keys per smem tile
constexpr int NSPLIT = 2;   // flash split-K
constexpr int VSTR = 24;    // V smem row stride in floats (bank-conflict-free pad)

// Dataset-fixed max shapes (B=4, S=2048) for static scratch.
constexpr int MAXB = 4;
constexpr int MAXS = 2048;
constexpr int BH   = MAXB * NH;       // 32
constexpr int BNS  = BH * MAXS;

// Split-K partials. g_o layout: [sp][bh][grp(8 d-pairs)][q] as float2.
__device__ float  g_m[NSPLIT * BNS];
__device__ float  g_l[NSPLIT * BNS];
__device__ float2 g_o[NSPLIT * BH * 8 * MAXS];

__device__ __forceinline__ float fast_exp2(float x) {
    float r; asm("ex2.approx.ftz.f32 %0, %1;" : "=f"(r) : "f"(x)); return r;
}
__device__ __forceinline__ uint32_t tf32r(float x) {   // round-to-nearest tf32
    uint32_t u; asm("cvt.rna.tf32.f32 %0, %1;" : "=r"(u) : "f"(x)); return u;
}
// m16n8k8 tf32 mma: D = A*B + C   (A row-major 16x8, B col-major 8x8, f32 accum)
__device__ __forceinline__ void mma8(
    float& d0, float& d1, float& d2, float& d3,
    uint32_t a0, uint32_t a1, uint32_t a2, uint32_t a3,
    uint32_t b0, uint32_t b1,
    float c0, float c1, float c2, float c3)
{
    asm("mma.sync.aligned.m16n8k8.row.col.f32.tf32.tf32.f32 "
        "{%0,%1,%2,%3},{%4,%5,%6,%7},{%8,%9},{%10,%11,%12,%13};"
        : "=f"(d0), "=f"(d1), "=f"(d2), "=f"(d3)
        : "r"(a0), "r"(a1), "r"(a2), "r"(a3), "r"(b0), "r"(b1),
          "f"(c0), "f"(c1), "f"(c2), "f"(c3));
}

__global__ __launch_bounds__(TPB) void mha_tc_kernel(
    const float* __restrict__ kv,     // [B, S, 2*HID]
    const float* __restrict__ qg,     // [B, S, HID]
    const int*   __restrict__ slen,   // [B]
    int S)
{
    // K stored d-permuted (d -> (d%4)*4 + d/4): row = 16 floats, LDS.128-friendly.
    __shared__ float Khi[TK * 16];
    __shared__ float Klo[TK * 16];
    __shared__ float Vhi[TK * VSTR];
    __shared__ float Vlo[TK * VSTR];

    const int tid  = threadIdx.x;
    const int warp = tid >> 5;
    const int lane = tid & 31;
    const int g    = lane >> 2;   // 0..7  (row group / key col / d col)
    const int t    = lane & 3;    // 0..3

    const int b  = blockIdx.z;
    const int h  = blockIdx.y;
    const int qb = blockIdx.x / NSPLIT;
    const int sp = blockIdx.x % NSPLIT;
    const int n  = slen[b];

    const int chunkN = (n + NSPLIT - 1) / NSPLIT;
    const int start  = sp * chunkN;
    const int end    = min(n, start + chunkN);

    const int qbase = qb * QBLK + warp * QW;

    // ---- Load Q fragments (rows g, g+8; d = t, t+4, t+8, t+12), fold scale ----
    const float scale = 4.0f * 1.4426950408889634f;   // sqrt(d_head) * log2(e)
    const float* qr0 = qg + ((size_t)b * S + qbase + g) * HID + h * DH;
    const float* qr1 = qr0 + 8 * HID;
    float qv0[4], qv1[4];
#pragma unroll
    for (int i = 0; i < 4; i++) {
        qv0[i] = qr0[t + 4 * i] * scale;
        qv1[i] = qr1[t + 4 * i] * scale;
    }
    uint32_t Ah1[4], Al1[4], Ah2[4], Al2[4];
    {
        // A frag order {a0,a1,a2,a3} = {(g,c),(g+8,c),(g,c+4),(g+8,c+4)}
        float v;
        Ah1[0] = tf32r(qv0[0]); v = qv0[0] - __uint_as_float(Ah1[0]); Al1[0] = tf32r(v);
        Ah1[1] = tf32r(qv1[0]); v = qv1[0] - __uint_as_float(Ah1[1]); Al1[1] = tf32r(v);
        Ah1[2] = tf32r(qv0[1]); v = qv0[1] - __uint_as_float(Ah1[2]); Al1[2] = tf32r(v);
        Ah1[3] = tf32r(qv1[1]); v = qv1[1] - __uint_as_float(Ah1[3]); Al1[3] = tf32r(v);
        Ah2[0] = tf32r(qv0[2]); v = qv0[2] - __uint_as_float(Ah2[0]); Al2[0] = tf32r(v);
        Ah2[1] = tf32r(qv1[2]); v = qv1[2] - __uint_as_float(Ah2[1]); Al2[1] = tf32r(v);
        Ah2[2] = tf32r(qv0[3]); v = qv0[3] - __uint_as_float(Ah2[2]); Al2[2] = tf32r(v);
        Ah2[3] = tf32r(qv1[3]); v = qv1[3] - __uint_as_float(Ah2[3]); Al2[3] = tf32r(v);
    }

    float m0 = -FLT_MAX, m1 = -FLT_MAX, l0 = 0.0f, l1 = 0.0f;
    float oA0 = 0, oA1 = 0, oA2 = 0, oA3 = 0;   // d 0..7   (PV mma 1 accum)
    float oB0 = 0, oB1 = 0, oB2 = 0, oB3 = 0;   // d 8..15  (PV mma 2 accum)

    const float* kbase = kv + ((size_t)b * S) * (2 * HID) + h * DH;
    const int srow = tid >> 2;   // staging: 0..31
    const int sseg = tid & 3;

// One 8-key chunk: 6 QK mmas (tf32x3), softmax, P-shuffle, 4 PV mmas.
#define TC_CHUNK(K0, MASKED)                                                    \
do {                                                                            \
    const uint4 kh4 = *reinterpret_cast<const uint4*>(&Khi[((K0) + g) * 16 + t * 4]); \
    const uint4 kl4 = *reinterpret_cast<const uint4*>(&Klo[((K0) + g) * 16 + t * 4]); \
    float cA0, cA1, cA2, cA3, cB0, cB1, cB2, cB3;                               \
    mma8(cA0,cA1,cA2,cA3, Ah1[0],Ah1[1],Ah1[2],Ah1[3], kh4.x,kh4.y, 0.f,0.f,0.f,0.f); \
    mma8(cA0,cA1,cA2,cA3, Al1[0],Al1[1],Al1[2],Al1[3], kh4.x,kh4.y, cA0,cA1,cA2,cA3); \
    mma8(cA0,cA1,cA2,cA3, Ah1[0],Ah1[1],Ah1[2],Ah1[3], kl4.x,kl4.y, cA0,cA1,cA2,cA3); \
    mma8(cB0,cB1,cB2,cB3, Ah2[0],Ah2[1],Ah2[2],Ah2[3], kh4.z,kh4.w, 0.f,0.f,0.f,0.f); \
    mma8(cB0,cB1,cB2,cB3, Al2[0],Al2[1],Al2[2],Al2[3], kh4.z,kh4.w, cB0,cB1,cB2,cB3); \
    mma8(cB0,cB1,cB2,cB3, Ah2[0],Ah2[1],Ah2[2],Ah2[3], kl4.z,kl4.w, cB0,cB1,cB2,cB3); \
    float s0 = cA0 + cB0, s1 = cA1 + cB1, s2 = cA2 + cB2, s3 = cA3 + cB3;       \
    if (MASKED) {                                                               \
        bool v0 = ((K0) + 2 * t)     < tn;                                      \
        bool v1 = ((K0) + 2 * t + 1) < tn;                                      \
        s0 = v0 ? s0 : -FLT_MAX;  s1 = v1 ? s1 : -FLT_MAX;                      \
        s2 = v0 ? s2 : -FLT_MAX;  s3 = v1 ? s3 : -FLT_MAX;                      \
    }                                                                           \
    float r0 = fmaxf(s0, s1), r1 = fmaxf(s2, s3);                               \
    r0 = fmaxf(r0, __shfl_xor_sync(0xffffffffu, r0, 1));                        \
    r0 = fmaxf(r0, __shfl_xor_sync(0xffffffffu, r0, 2));                        \
    r1 = fmaxf(r1, __shfl_xor_sync(0xffffffffu, r1, 1));                        \
    r1 = fmaxf(r1, __shfl_xor_sync(0xffffffffu, r1, 2));                        \
    float mn0 = fmaxf(m0, r0), mn1 = fmaxf(m1, r1);                             \
    float co0 = fast_exp2(m0 - mn0), co1 = fast_exp2(m1 - mn1);                 \
    m0 = mn0; m1 = mn1;                                                         \
    uint32_t u0 = tf32r(fast_exp2(s0 - mn0));                                   \
    uint32_t u1 = tf32r(fast_exp2(s1 - mn0));                                   \
    uint32_t u2 = tf32r(fast_exp2(s2 - mn1));                                   \
    uint32_t u3 = tf32r(fast_exp2(s3 - mn1));                                   \
    l0 = l0 * co0 + (__uint_as_float(u0) + __uint_as_float(u1));                \
    l1 = l1 * co1 + (__uint_as_float(u2) + __uint_as_float(u3));                \
    oA0 *= co0; oA1 *= co0; oA2 *= co1; oA3 *= co1;                             \
    oB0 *= co0; oB1 *= co0; oB2 *= co1; oB3 *= co1;                             \
    /* P: C-layout (cols 2t,2t+1) -> A-layout (cols t, t+4) via quad shuffles */ \
    int srcA = (lane & ~3) | (t >> 1);                                          \
    int srcB = srcA + 2;                                                        \
    uint32_t x0 = __shfl_sync(0xffffffffu, u0, srcA);                           \
    uint32_t x1 = __shfl_sync(0xffffffffu, u1, srcA);                           \
    uint32_t y0 = __shfl_sync(0xffffffffu, u0, srcB);                           \
    uint32_t y1 = __shfl_sync(0xffffffffu, u1, srcB);                           \
    uint32_t z0 = __shfl_sync(0xffffffffu, u2, srcA);                           \
    uint32_t z1 = __shfl_sync(0xffffffffu, u3, srcA);                           \
    uint32_t w0 = __shfl_sync(0xffffffffu, u2, srcB);                           \
    uint32_t w1 = __shfl_sync(0xffffffffu, u3, srcB);                           \
    uint32_t pa0 = (t & 1) ? x1 : x0;   /* (row g,   col t)   */                \
    uint32_t pa1 = (t & 1) ? z1 : z0;   /* (row g+8, col t)   */                \
    uint32_t pa2 = (t & 1) ? y1 : y0;   /* (row g,   col t+4) */                \
    uint32_t pa3 = (t & 1) ? w1 : w0;   /* (row g+8, col t+4) */                \
    /* V B-frags: b0 = V[K0+t][d], b1 = V[K0+t+4][d] */                         \
    const int vo0 = ((K0) + t) * VSTR, vo1 = ((K0) + t + 4) * VSTR;             \
    uint32_t vh0 = __float_as_uint(Vhi[vo0 + g]);                               \
    uint32_t vh1 = __float_as_uint(Vhi[vo1 + g]);                               \
    uint32_t vh2 = __float_as_uint(Vhi[vo0 + g + 8]);                           \
    uint32_t vh3 = __float_as_uint(Vhi[vo1 + g + 8]);                           \
    uint32_t vl0 = __float_as_uint(Vlo[vo0 + g]);                               \
    uint32_t vl1 = __float_as_uint(Vlo[vo1 + g]);                               \
    uint32_t vl2 = __float_as_uint(Vlo[vo0 + g + 8]);                           \
    uint32_t vl3 = __float_as_uint(Vlo[vo1 + g + 8]);                           \
    mma8(oA0,oA1,oA2,oA3, pa0,pa1,pa2,pa3, vh0,vh1, oA0,oA1,oA2,oA3);           \
    mma8(oB0,oB1,oB2,oB3, pa0,pa1,pa2,pa3, vh2,vh3, oB0,oB1,oB2,oB3);           \
    mma8(oA0,oA1,oA2,oA3, pa0,pa1,pa2,pa3, vl0,vl1, oA0,oA1,oA2,oA3);           \
    mma8(oB0,oB1,oB2,oB3, pa0,pa1,pa2,pa3, vl2,vl3, oB0,oB1,oB2,oB3);           \
} while (0)

    for (int t0 = start; t0 < end; t0 += TK) {
        const int tn = min(TK, end - t0);

        __syncthreads();
        // ---- Stage K (split hi/lo, d-permuted) and V (split hi/lo, padded) ----
#pragma unroll
        for (int r = 0; r < TK; r += 32) {
            const int rr = srow + r;
            float4 k4 = make_float4(0.f, 0.f, 0.f, 0.f);
            float4 v4 = make_float4(0.f, 0.f, 0.f, 0.f);
            if (rr < tn) {
                const float* src = kbase + (size_t)(t0 + rr) * (2 * HID) + sseg * 4;
                k4 = *reinterpret_cast<const float4*>(src);
                v4 = *reinterpret_cast<const float4*>(src + HID);
            }
            // K: element j has d = sseg*4+j -> permuted slot j*4 + sseg
            const float ke[4] = {k4.x, k4.y, k4.z, k4.w};
#pragma unroll
            for (int j = 0; j < 4; j++) {
                uint32_t hi = tf32r(ke[j]);
                uint32_t lo = tf32r(ke[j] - __uint_as_float(hi));
                Khi[rr * 16 + j * 4 + sseg] = __uint_as_float(hi);
                Klo[rr * 16 + j * 4 + sseg] = __uint_as_float(lo);
            }
            // V: contiguous d, padded row
            const float ve[4] = {v4.x, v4.y, v4.z, v4.w};
            float vh[4], vl[4];
#pragma unroll
            for (int j = 0; j < 4; j++) {
                uint32_t hi = tf32r(ve[j]);
                vh[j] = __uint_as_float(hi);
                vl[j] = __uint_as_float(tf32r(ve[j] - vh[j]));
            }
            *reinterpret_cast<float4*>(&Vhi[rr * VSTR + sseg * 4]) =
                make_float4(vh[0], vh[1], vh[2], vh[3]);
            *reinterpret_cast<float4*>(&Vlo[rr * VSTR + sseg * 4]) =
                make_float4(vl[0], vl[1], vl[2], vl[3]);
        }
        __syncthreads();

        const int nfull = tn >> 3;
        for (int ic = 0; ic < nfull; ic++) {
            TC_CHUNK(ic * 8, 0);
        }
        if (tn & 7) {
            TC_CHUNK(nfull * 8, 1);
        }
    }

    // ---- Finalize: quad-reduce l (m already quad-uniform), write partials ----
    l0 += __shfl_xor_sync(0xffffffffu, l0, 1);
    l0 += __shfl_xor_sync(0xffffffffu, l0, 2);
    l1 += __shfl_xor_sync(0xffffffffu, l1, 1);
    l1 += __shfl_xor_sync(0xffffffffu, l1, 2);

    const int bh_ = b * NH + h;
    const int q0g = qbase + g;
    const int q1g = qbase + g + 8;
    if (t == 0) {
        g_m[sp * BNS + bh_ * S + q0g] = m0;
        g_l[sp * BNS + bh_ * S + q0g] = l0;
        g_m[sp * BNS + bh_ * S + q1g] = m1;
        g_l[sp * BNS + bh_ * S + q1g] = l1;
    }
    const size_t ob = (size_t)(sp * BH + bh_) * 8;
    g_o[(ob + t    ) * S + q0g] = make_float2(oA0, oA1);
    g_o[(ob + t + 4) * S + q0g] = make_float2(oB0, oB1);
    g_o[(ob + t    ) * S + q1g] = make_float2(oA2, oA3);
    g_o[(ob + t + 4) * S + q1g] = make_float2(oB2, oB3);
}

__global__ __launch_bounds__(256) void mha_combine_kernel(
    float* __restrict__ out, int S, int total)   // total = B*NH*S
{
    int idx = blockIdx.x * 256 + threadIdx.x;
    if (idx >= total) return;
    const int q  = idx % S;
    const int bh = idx / S;
    const int h  = bh % NH;
    const int b  = bh / NH;
    const int base = bh * S + q;

    float m[NSPLIT], l[NSPLIT];
    float mm = -FLT_MAX;
#pragma unroll
    for (int sp = 0; sp < NSPLIT; sp++) {
        m[sp] = g_m[sp * BNS + base];
        l[sp] = g_l[sp * BNS + base];
        mm = fmaxf(mm, m[sp]);
    }
    float a[NSPLIT];
    float denom = 0.0f;
#pragma unroll
    for (int sp = 0; sp < NSPLIT; sp++) {
        a[sp] = fast_exp2(m[sp] - mm);     // empty split: m=-FLT_MAX -> 0
        denom = fmaf(l[sp], a[sp], denom);
    }
    const float inv = 1.0f / denom;        // n>=1 guarantees split-0 l>0
#pragma unroll
    for (int sp = 0; sp < NSPLIT; sp++) a[sp] *= inv;

    float* op = out + ((size_t)b * S + q) * HID + h * DH;
#pragma unroll
    for (int grp = 0; grp < 8; grp++) {
        float2 acc = make_float2(0.f, 0.f);
#pragma unroll
        for (int sp = 0; sp < NSPLIT; sp++) {
            float2 o = g_o[((size_t)(sp * BH + bh) * 8 + grp) * S + q];
            acc.x = fmaf(o.x, a[sp], acc.x);
            acc.y = fmaf(o.y, a[sp], acc.y);
        }
        reinterpret_cast<float2*>(op)[grp] = acc;
    }
}

extern "C" void kernel_launch(void* const* d_in, const int* in_sizes, int n_in,
                              void* d_out, int out_size)
{
    const float* kv = (const float*)d_in[0];   // key_and_value [B,S,256]
    const float* qg = (const float*)d_in[1];   // query         [B,S,128]
    const int*   sl = (const int*)  d_in[2];   // seq_len       [B,1]

    const int B = in_sizes[2];                 // [B,1] ints
    const int S = in_sizes[1] / (B * HID);

    dim3 grid((S / QBLK) * NSPLIT, NH, B);
    mha_tc_kernel<<<grid, TPB>>>(kv, qg, sl, S);

    const int total = B * NH * S;
    mha_combine_kernel<<<(total + 255) / 256, 256>>>((float*)d_out, S, total);
}

// round 10
// speedup vs baseline: 1.2974x; 1.2974x over previous
#include <cuda_runtime.h>
#include <cfloat>
#include <cstdint>

// Problem constants (fixed by reference: HIDDEN=128, NUM_HEADS=8)
constexpr int DH   = 16;
constexpr int NH   = 8;
constexpr int HID  = 128;
constexpr int TPB  = 128;   // 4 warps
constexpr int QW   = 16;    // queries per warp (mma M)
constexpr int QBLK = 64;    // queries per block
constexpr int TK   = 128;   // keys per smem tile
constexpr int NSPLIT = 2;   // flash split-K
constexpr int VSTR = 24;    // V smem row stride in floats (bank-conflict-free pad)

// Dataset-fixed max shapes (B=4, S=2048) for static scratch.
constexpr int MAXB = 4;
constexpr int MAXS = 2048;
constexpr int BH   = MAXB * NH;       // 32
constexpr int BNS  = BH * MAXS;

// Split-K partials. g_o layout: [sp][bh][grp(8 d-pairs)][q] as float2.
__device__ float  g_m[NSPLIT * BNS];
__device__ float  g_l[NSPLIT * BNS];
__device__ float2 g_o[NSPLIT * BH * 8 * MAXS];

__device__ __forceinline__ float fast_exp2(float x) {
    float r; asm("ex2.approx.ftz.f32 %0, %1;" : "=f"(r) : "f"(x)); return r;
}
__device__ __forceinline__ uint32_t tf32r(float x) {   // round-to-nearest tf32
    uint32_t u; asm("cvt.rna.tf32.f32 %0, %1;" : "=r"(u) : "f"(x)); return u;
}
// m16n8k8 tf32 mma: D = A*B + C   (A row-major 16x8, B col-major 8x8, f32 accum)
__device__ __forceinline__ void mma8(
    float& d0, float& d1, float& d2, float& d3,
    uint32_t a0, uint32_t a1, uint32_t a2, uint32_t a3,
    uint32_t b0, uint32_t b1,
    float c0, float c1, float c2, float c3)
{
    asm("mma.sync.aligned.m16n8k8.row.col.f32.tf32.tf32.f32 "
        "{%0,%1,%2,%3},{%4,%5,%6,%7},{%8,%9},{%10,%11,%12,%13};"
        : "=f"(d0), "=f"(d1), "=f"(d2), "=f"(d3)
        : "r"(a0), "r"(a1), "r"(a2), "r"(a3), "r"(b0), "r"(b1),
          "f"(c0), "f"(c1), "f"(c2), "f"(c3));
}

__global__ __launch_bounds__(TPB) void mha_tc_kernel(
    const float* __restrict__ kv,     // [B, S, 2*HID]
    const float* __restrict__ qg,     // [B, S, HID]
    const int*   __restrict__ slen,   // [B]
    int S)
{
    // K stored d-permuted (d -> (d%4)*4 + d/4): row = 16 floats, LDS.128-friendly.
    __shared__ float Khi[TK * 16];
    __shared__ float Klo[TK * 16];
    __shared__ float Vhi[TK * VSTR];   // V rounded to tf32 (RNA), no lo split

    const int tid  = threadIdx.x;
    const int warp = tid >> 5;
    const int lane = tid & 31;
    const int g    = lane >> 2;   // 0..7
    const int t    = lane & 3;    // 0..3

    const int b  = blockIdx.z;
    const int h  = blockIdx.y;
    const int qb = blockIdx.x / NSPLIT;
    const int sp = blockIdx.x % NSPLIT;
    const int n  = slen[b];

    const int chunkN = (n + NSPLIT - 1) / NSPLIT;
    const int start  = sp * chunkN;
    const int end    = min(n, start + chunkN);

    const int qbase = qb * QBLK + warp * QW;

    // ---- Q fragments (rows g, g+8; d = t, t+4, t+8, t+12), fold scale ----
    const float scale = 4.0f * 1.4426950408889634f;   // sqrt(d_head) * log2(e)
    const float* qr0 = qg + ((size_t)b * S + qbase + g) * HID + h * DH;
    const float* qr1 = qr0 + 8 * HID;
    float qv0[4], qv1[4];
#pragma unroll
    for (int i = 0; i < 4; i++) {
        qv0[i] = qr0[t + 4 * i] * scale;
        qv1[i] = qr1[t + 4 * i] * scale;
    }
    uint32_t Ah1[4], Al1[4], Ah2[4], Al2[4];
    {
        float v;
        Ah1[0] = tf32r(qv0[0]); v = qv0[0] - __uint_as_float(Ah1[0]); Al1[0] = tf32r(v);
        Ah1[1] = tf32r(qv1[0]); v = qv1[0] - __uint_as_float(Ah1[1]); Al1[1] = tf32r(v);
        Ah1[2] = tf32r(qv0[1]); v = qv0[1] - __uint_as_float(Ah1[2]); Al1[2] = tf32r(v);
        Ah1[3] = tf32r(qv1[1]); v = qv1[1] - __uint_as_float(Ah1[3]); Al1[3] = tf32r(v);
        Ah2[0] = tf32r(qv0[2]); v = qv0[2] - __uint_as_float(Ah2[0]); Al2[0] = tf32r(v);
        Ah2[1] = tf32r(qv1[2]); v = qv1[2] - __uint_as_float(Ah2[1]); Al2[1] = tf32r(v);
        Ah2[2] = tf32r(qv0[3]); v = qv0[3] - __uint_as_float(Ah2[2]); Al2[2] = tf32r(v);
        Ah2[3] = tf32r(qv1[3]); v = qv1[3] - __uint_as_float(Ah2[3]); Al2[3] = tf32r(v);
    }

    float m0 = -FLT_MAX, m1 = -FLT_MAX, l0 = 0.0f, l1 = 0.0f;
    float oA0 = 0, oA1 = 0, oA2 = 0, oA3 = 0;   // d 0..7
    float oB0 = 0, oB1 = 0, oB2 = 0, oB3 = 0;   // d 8..15

    const float* kbase = kv + ((size_t)b * S) * (2 * HID) + h * DH;
    const int srow = tid >> 2;
    const int sseg = tid & 3;

// 16-key chunk: 12 QK mmas (tf32x3, two independent 8-key groups), joint
// softmax, two P conversions, 4 PV mmas (V hi-only).
#define TC_CHUNK16(K0, MASKED)                                                  \
do {                                                                            \
    const uint4 kh4a = *reinterpret_cast<const uint4*>(&Khi[((K0) + g) * 16 + t * 4]);     \
    const uint4 kl4a = *reinterpret_cast<const uint4*>(&Klo[((K0) + g) * 16 + t * 4]);     \
    const uint4 kh4b = *reinterpret_cast<const uint4*>(&Khi[((K0) + 8 + g) * 16 + t * 4]); \
    const uint4 kl4b = *reinterpret_cast<const uint4*>(&Klo[((K0) + 8 + g) * 16 + t * 4]); \
    float cA0,cA1,cA2,cA3, cB0,cB1,cB2,cB3;                                     \
    float dA0,dA1,dA2,dA3, dB0,dB1,dB2,dB3;                                     \
    mma8(cA0,cA1,cA2,cA3, Ah1[0],Ah1[1],Ah1[2],Ah1[3], kh4a.x,kh4a.y, 0.f,0.f,0.f,0.f); \
    mma8(dA0,dA1,dA2,dA3, Ah1[0],Ah1[1],Ah1[2],Ah1[3], kh4b.x,kh4b.y, 0.f,0.f,0.f,0.f); \
    mma8(cA0,cA1,cA2,cA3, Al1[0],Al1[1],Al1[2],Al1[3], kh4a.x,kh4a.y, cA0,cA1,cA2,cA3); \
    mma8(dA0,dA1,dA2,dA3, Al1[0],Al1[1],Al1[2],Al1[3], kh4b.x,kh4b.y, dA0,dA1,dA2,dA3); \
    mma8(cA0,cA1,cA2,cA3, Ah1[0],Ah1[1],Ah1[2],Ah1[3], kl4a.x,kl4a.y, cA0,cA1,cA2,cA3); \
    mma8(dA0,dA1,dA2,dA3, Ah1[0],Ah1[1],Ah1[2],Ah1[3], kl4b.x,kl4b.y, dA0,dA1,dA2,dA3); \
    mma8(cB0,cB1,cB2,cB3, Ah2[0],Ah2[1],Ah2[2],Ah2[3], kh4a.z,kh4a.w, 0.f,0.f,0.f,0.f); \
    mma8(dB0,dB1,dB2,dB3, Ah2[0],Ah2[1],Ah2[2],Ah2[3], kh4b.z,kh4b.w, 0.f,0.f,0.f,0.f); \
    mma8(cB0,cB1,cB2,cB3, Al2[0],Al2[1],Al2[2],Al2[3], kh4a.z,kh4a.w, cB0,cB1,cB2,cB3); \
    mma8(dB0,dB1,dB2,dB3, Al2[0],Al2[1],Al2[2],Al2[3], kh4b.z,kh4b.w, dB0,dB1,dB2,dB3); \
    mma8(cB0,cB1,cB2,cB3, Ah2[0],Ah2[1],Ah2[2],Ah2[3], kl4a.z,kl4a.w, cB0,cB1,cB2,cB3); \
    mma8(dB0,dB1,dB2,dB3, Ah2[0],Ah2[1],Ah2[2],Ah2[3], kl4b.z,kl4b.w, dB0,dB1,dB2,dB3); \
    float s0 = cA0 + cB0, s1 = cA1 + cB1, s2 = cA2 + cB2, s3 = cA3 + cB3;       \
    float s4 = dA0 + dB0, s5 = dA1 + dB1, s6 = dA2 + dB2, s7 = dA3 + dB3;       \
    if (MASKED) {                                                               \
        bool v0 = ((K0) + 2 * t)     < tn;                                      \
        bool v1 = ((K0) + 2 * t + 1) < tn;                                      \
        bool v2 = ((K0) + 8 + 2 * t)     < tn;                                  \
        bool v3 = ((K0) + 8 + 2 * t + 1) < tn;                                  \
        s0 = v0 ? s0 : -FLT_MAX;  s1 = v1 ? s1 : -FLT_MAX;                      \
        s2 = v0 ? s2 : -FLT_MAX;  s3 = v1 ? s3 : -FLT_MAX;                      \
        s4 = v2 ? s4 : -FLT_MAX;  s5 = v3 ? s5 : -FLT_MAX;                      \
        s6 = v2 ? s6 : -FLT_MAX;  s7 = v3 ? s7 : -FLT_MAX;                      \
    }                                                                           \
    float r0 = fmaxf(fmaxf(s0, s1), fmaxf(s4, s5));                             \
    float r1 = fmaxf(fmaxf(s2, s3), fmaxf(s6, s7));                             \
    r0 = fmaxf(r0, __shfl_xor_sync(0xffffffffu, r0, 1));                        \
    r0 = fmaxf(r0, __shfl_xor_sync(0xffffffffu, r0, 2));                        \
    r1 = fmaxf(r1, __shfl_xor_sync(0xffffffffu, r1, 1));                        \
    r1 = fmaxf(r1, __shfl_xor_sync(0xffffffffu, r1, 2));                        \
    float mn0 = fmaxf(m0, r0), mn1 = fmaxf(m1, r1);                             \
    float co0 = fast_exp2(m0 - mn0), co1 = fast_exp2(m1 - mn1);                 \
    m0 = mn0; m1 = mn1;                                                         \
    uint32_t u0 = tf32r(fast_exp2(s0 - mn0));                                   \
    uint32_t u1 = tf32r(fast_exp2(s1 - mn0));                                   \
    uint32_t u2 = tf32r(fast_exp2(s2 - mn1));                                   \
    uint32_t u3 = tf32r(fast_exp2(s3 - mn1));                                   \
    uint32_t u4 = tf32r(fast_exp2(s4 - mn0));                                   \
    uint32_t u5 = tf32r(fast_exp2(s5 - mn0));                                   \
    uint32_t u6 = tf32r(fast_exp2(s6 - mn1));                                   \
    uint32_t u7 = tf32r(fast_exp2(s7 - mn1));                                   \
    l0 = l0 * co0 + ((__uint_as_float(u0) + __uint_as_float(u1))                \
                   + (__uint_as_float(u4) + __uint_as_float(u5)));              \
    l1 = l1 * co1 + ((__uint_as_float(u2) + __uint_as_float(u3))                \
                   + (__uint_as_float(u6) + __uint_as_float(u7)));              \
    oA0 *= co0; oA1 *= co0; oA2 *= co1; oA3 *= co1;                             \
    oB0 *= co0; oB1 *= co0; oB2 *= co1; oB3 *= co1;                             \
    /* P conversions: C-layout (cols 2t,2t+1) -> A-layout (cols t, t+4) */      \
    int srcA = (lane & ~3) | (t >> 1);                                          \
    int srcB = srcA + 2;                                                        \
    uint32_t x0 = __shfl_sync(0xffffffffu, u0, srcA);                           \
    uint32_t x1 = __shfl_sync(0xffffffffu, u1, srcA);                           \
    uint32_t y0 = __shfl_sync(0xffffffffu, u0, srcB);                           \
    uint32_t y1 = __shfl_sync(0xffffffffu, u1, srcB);                           \
    uint32_t z0 = __shfl_sync(0xffffffffu, u2, srcA);                           \
    uint32_t z1 = __shfl_sync(0xffffffffu, u3, srcA);                           \
    uint32_t w0 = __shfl_sync(0xffffffffu, u2, srcB);                           \
    uint32_t w1 = __shfl_sync(0xffffffffu, u3, srcB);                           \
    uint32_t pa0 = (t & 1) ? x1 : x0;                                           \
    uint32_t pa1 = (t & 1) ? z1 : z0;                                           \
    uint32_t pa2 = (t & 1) ? y1 : y0;                                           \
    uint32_t pa3 = (t & 1) ? w1 : w0;                                           \
    x0 = __shfl_sync(0xffffffffu, u4, srcA);                                    \
    x1 = __shfl_sync(0xffffffffu, u5, srcA);                                    \
    y0 = __shfl_sync(0xffffffffu, u4, srcB);                                    \
    y1 = __shfl_sync(0xffffffffu, u5, srcB);                                    \
    z0 = __shfl_sync(0xffffffffu, u6, srcA);                                    \
    z1 = __shfl_sync(0xffffffffu, u7, srcA);                                    \
    w0 = __shfl_sync(0xffffffffu, u6, srcB);                                    \
    w1 = __shfl_sync(0xffffffffu, u7, srcB);                                    \
    uint32_t pb0 = (t & 1) ? x1 : x0;                                           \
    uint32_t pb1 = (t & 1) ? z1 : z0;                                           \
    uint32_t pb2 = (t & 1) ? y1 : y0;                                           \
    uint32_t pb3 = (t & 1) ? w1 : w0;                                           \
    /* V B-frags (hi only) */                                                   \
    const int vo0 = ((K0) + t) * VSTR,     vo1 = ((K0) + t + 4) * VSTR;         \
    const int vo2 = ((K0) + 8 + t) * VSTR, vo3 = ((K0) + 12 + t) * VSTR;        \
    uint32_t vh0 = __float_as_uint(Vhi[vo0 + g]);                               \
    uint32_t vh1 = __float_as_uint(Vhi[vo1 + g]);                               \
    uint32_t vh2 = __float_as_uint(Vhi[vo0 + g + 8]);                           \
    uint32_t vh3 = __float_as_uint(Vhi[vo1 + g + 8]);                           \
    uint32_t wh0 = __float_as_uint(Vhi[vo2 + g]);                               \
    uint32_t wh1 = __float_as_uint(Vhi[vo3 + g]);                               \
    uint32_t wh2 = __float_as_uint(Vhi[vo2 + g + 8]);                           \
    uint32_t wh3 = __float_as_uint(Vhi[vo3 + g + 8]);                           \
    mma8(oA0,oA1,oA2,oA3, pa0,pa1,pa2,pa3, vh0,vh1, oA0,oA1,oA2,oA3);           \
    mma8(oB0,oB1,oB2,oB3, pa0,pa1,pa2,pa3, vh2,vh3, oB0,oB1,oB2,oB3);           \
    mma8(oA0,oA1,oA2,oA3, pb0,pb1,pb2,pb3, wh0,wh1, oA0,oA1,oA2,oA3);           \
    mma8(oB0,oB1,oB2,oB3, pb0,pb1,pb2,pb3, wh2,wh3, oB0,oB1,oB2,oB3);           \
} while (0)

    for (int t0 = start; t0 < end; t0 += TK) {
        const int tn = min(TK, end - t0);

        __syncthreads();
        // ---- Stage K (hi/lo, d-permuted) and V (tf32-RNA, padded rows) ----
#pragma unroll
        for (int r = 0; r < TK; r += 32) {
            const int rr = srow + r;
            float4 k4 = make_float4(0.f, 0.f, 0.f, 0.f);
            float4 v4 = make_float4(0.f, 0.f, 0.f, 0.f);
            if (rr < tn) {
                const float* src = kbase + (size_t)(t0 + rr) * (2 * HID) + sseg * 4;
                k4 = *reinterpret_cast<const float4*>(src);
                v4 = *reinterpret_cast<const float4*>(src + HID);
            }
            const float ke[4] = {k4.x, k4.y, k4.z, k4.w};
#pragma unroll
            for (int j = 0; j < 4; j++) {
                uint32_t hi = tf32r(ke[j]);
                uint32_t lo = tf32r(ke[j] - __uint_as_float(hi));
                Khi[rr * 16 + j * 4 + sseg] = __uint_as_float(hi);
                Klo[rr * 16 + j * 4 + sseg] = __uint_as_float(lo);
            }
            *reinterpret_cast<float4*>(&Vhi[rr * VSTR + sseg * 4]) = make_float4(
                __uint_as_float(tf32r(v4.x)), __uint_as_float(tf32r(v4.y)),
                __uint_as_float(tf32r(v4.z)), __uint_as_float(tf32r(v4.w)));
        }
        __syncthreads();

        const int nfull = tn >> 4;
        for (int ic = 0; ic < nfull; ic++) {
            TC_CHUNK16(ic * 16, 0);
        }
        if (tn & 15) {
            TC_CHUNK16(nfull * 16, 1);
        }
    }

    // ---- Finalize: quad-reduce l (m already quad-uniform), write partials ----
    l0 += __shfl_xor_sync(0xffffffffu, l0, 1);
    l0 += __shfl_xor_sync(0xffffffffu, l0, 2);
    l1 += __shfl_xor_sync(0xffffffffu, l1, 1);
    l1 += __shfl_xor_sync(0xffffffffu, l1, 2);

    const int bh_ = b * NH + h;
    const int q0g = qbase + g;
    const int q1g = qbase + g + 8;
    if (t == 0) {
        g_m[sp * BNS + bh_ * S + q0g] = m0;
        g_l[sp * BNS + bh_ * S + q0g] = l0;
        g_m[sp * BNS + bh_ * S + q1g] = m1;
        g_l[sp * BNS + bh_ * S + q1g] = l1;
    }
    const size_t ob = (size_t)(sp * BH + bh_) * 8;
    g_o[(ob + t    ) * S + q0g] = make_float2(oA0, oA1);
    g_o[(ob + t + 4) * S + q0g] = make_float2(oB0, oB1);
    g_o[(ob + t    ) * S + q1g] = make_float2(oA2, oA3);
    g_o[(ob + t + 4) * S + q1g] = make_float2(oB2, oB3);
}

__global__ __launch_bounds__(256) void mha_combine_kernel(
    float* __restrict__ out, int S, int total)   // total = B*NH*S
{
    int idx = blockIdx.x * 256 + threadIdx.x;
    if (idx >= total) return;
    const int q  = idx % S;
    const int bh = idx / S;
    const int h  = bh % NH;
    const int b  = bh / NH;
    const int base = bh * S + q;

    float m[NSPLIT], l[NSPLIT];
    float mm = -FLT_MAX;
#pragma unroll
    for (int sp = 0; sp < NSPLIT; sp++) {
        m[sp] = g_m[sp * BNS + base];
        l[sp] = g_l[sp * BNS + base];
        mm = fmaxf(mm, m[sp]);
    }
    float a[NSPLIT];
    float denom = 0.0f;
#pragma unroll
    for (int sp = 0; sp < NSPLIT; sp++) {
        a[sp] = fast_exp2(m[sp] - mm);     // empty split: m=-FLT_MAX -> 0
        denom = fmaf(l[sp], a[sp], denom);
    }
    const float inv = 1.0f / denom;        // n>=1 guarantees split-0 l>0
#pragma unroll
    for (int sp = 0; sp < NSPLIT; sp++) a[sp] *= inv;

    float* op = out + ((size_t)b * S + q) * HID + h * DH;
#pragma unroll
    for (int grp = 0; grp < 8; grp++) {
        float2 acc = make_float2(0.f, 0.f);
#pragma unroll
        for (int sp = 0; sp < NSPLIT; sp++) {
            float2 o = g_o[((size_t)(sp * BH + bh) * 8 + grp) * S + q];
            acc.x = fmaf(o.x, a[sp], acc.x);
            acc.y = fmaf(o.y, a[sp], acc.y);
        }
        reinterpret_cast<float2*>(op)[grp] = acc;
    }
}

extern "C" void kernel_launch(void* const* d_in, const int* in_sizes, int n_in,
                              void* d_out, int out_size)
{
    const float* kv = (const float*)d_in[0];   // key_and_value [B,S,256]
    const float* qg = (const float*)d_in[1];   // query         [B,S,128]
    const int*   sl = (const int*)  d_in[2];   // seq_len       [B,1]

    const int B = in_sizes[2];                 // [B,1] ints
    const int S = in_sizes[1] / (B * HID);

    dim3 grid((S / QBLK) * NSPLIT, NH, B);
    mha_tc_kernel<<<grid, TPB>>>(kv, qg, sl, S);

    const int total = B * NH * S;
    mha_combine_kernel<<<(total + 255) / 256, 256>>>((float*)d_out, S, total);
}

// round 12
// speedup vs baseline: 1.8824x; 1.4508x over previous
#include <cuda_runtime.h>
#include <cfloat>
#include <cstdint>

// Problem constants (fixed by reference: HIDDEN=128, NUM_HEADS=8)
constexpr int DH   = 16;
constexpr int NH   = 8;
constexpr int HID  = 128;
constexpr int TPB  = 128;   // 4 warps
constexpr int QW   = 16;    // queries per warp (mma M)
constexpr int QBLK = 64;    // queries per block
constexpr int TK   = 128;   // keys per smem tile
constexpr int NSPLIT = 2;   // flash split-K
constexpr int VSTR = 20;    // V smem row stride (floats): conflict-free for rows 2t,2t+1

// Dataset-fixed max shapes (B=4, S=2048) for static scratch.
constexpr int MAXB = 4;
constexpr int MAXS = 2048;
constexpr int BH   = MAXB * NH;       // 32
constexpr int BNS  = BH * MAXS;

// Split-K partials. g_o layout: [sp][bh][grp(8 d-pairs)][q] as float2.
__device__ float  g_m[NSPLIT * BNS];
__device__ float  g_l[NSPLIT * BNS];
__device__ float2 g_o[NSPLIT * BH * 8 * MAXS];

__device__ __forceinline__ float fast_exp2(float x) {
    float r; asm("ex2.approx.ftz.f32 %0, %1;" : "=f"(r) : "f"(x)); return r;
}
__device__ __forceinline__ uint32_t tf32r(float x) {   // round-to-nearest tf32
    uint32_t u; asm("cvt.rna.tf32.f32 %0, %1;" : "=r"(u) : "f"(x)); return u;
}
// bf16x2 pack: low half = lo_elem, high half = hi_elem
__device__ __forceinline__ uint32_t packbf2(float lo_elem, float hi_elem) {
    uint32_t r;
    asm("cvt.rn.bf16x2.f32 %0, %1, %2;" : "=r"(r) : "f"(hi_elem), "f"(lo_elem));
    return r;
}
// RNE bf16 split: x = hf + residual (hf exactly bf16-representable)
__device__ __forceinline__ void bf16_split(float x, float& hf, float& lf) {
    uint32_t xb = __float_as_uint(x);
    uint32_t r  = (xb + 0x7FFFu + ((xb >> 16) & 1u)) & 0xFFFF0000u;
    hf = __uint_as_float(r);
    lf = x - hf;
}

// m16n8k16 bf16 mma: D = A*B + C
__device__ __forceinline__ void mma16b(
    float& d0, float& d1, float& d2, float& d3,
    uint32_t a0, uint32_t a1, uint32_t a2, uint32_t a3,
    uint32_t b0, uint32_t b1,
    float c0, float c1, float c2, float c3)
{
    asm("mma.sync.aligned.m16n8k16.row.col.f32.bf16.bf16.f32 "
        "{%0,%1,%2,%3},{%4,%5,%6,%7},{%8,%9},{%10,%11,%12,%13};"
        : "=f"(d0), "=f"(d1), "=f"(d2), "=f"(d3)
        : "r"(a0), "r"(a1), "r"(a2), "r"(a3), "r"(b0), "r"(b1),
          "f"(c0), "f"(c1), "f"(c2), "f"(c3));
}
// m16n8k8 tf32 mma: D = A*B + C
__device__ __forceinline__ void mma8(
    float& d0, float& d1, float& d2, float& d3,
    uint32_t a0, uint32_t a1, uint32_t a2, uint32_t a3,
    uint32_t b0, uint32_t b1,
    float c0, float c1, float c2, float c3)
{
    asm("mma.sync.aligned.m16n8k8.row.col.f32.tf32.tf32.f32 "
        "{%0,%1,%2,%3},{%4,%5,%6,%7},{%8,%9},{%10,%11,%12,%13};"
        : "=f"(d0), "=f"(d1), "=f"(d2), "=f"(d3)
        : "r"(a0), "r"(a1), "r"(a2), "r"(a3), "r"(b0), "r"(b1),
          "f"(c0), "f"(c1), "f"(c2), "f"(c3));
}

__global__ __launch_bounds__(TPB) void mha_tc_kernel(
    const float* __restrict__ kv,     // [B, S, 2*HID]
    const float* __restrict__ qg,     // [B, S, HID]
    const int*   __restrict__ slen,   // [B]
    int S)
{
    // K rows: 8 words of bf16x2, word order (d0,1)(d8,9)(d2,3)(d10,11)(d4,5)(d12,13)(d6,7)(d14,15)
    // so thread t's B-frag {(2t,2t+1),(2t+8,2t+9)} is ONE uint2 at word 2t.
    __shared__ uint32_t KhiW[TK * 8];
    __shared__ uint32_t KloW[TK * 8];
    __shared__ float    Vhi[TK * VSTR];   // V rounded to tf32 (RNA)

    const int tid  = threadIdx.x;
    const int warp = tid >> 5;
    const int lane = tid & 31;
    const int g    = lane >> 2;   // 0..7
    const int t    = lane & 3;    // 0..3

    const int b  = blockIdx.z;
    const int h  = blockIdx.y;
    const int qb = blockIdx.x / NSPLIT;
    const int sp = blockIdx.x % NSPLIT;
    const int n  = slen[b];

    const int chunkN = (n + NSPLIT - 1) / NSPLIT;
    const int start  = sp * chunkN;
    const int end    = min(n, start + chunkN);

    const int qbase = qb * QBLK + warp * QW;

    // ---- Q fragments (rows g, g+8; d = 2t,2t+1,2t+8,2t+9), bf16x2 hi/lo ----
    const float scale = 4.0f * 1.4426950408889634f;   // sqrt(d_head) * log2(e)
    uint32_t Ahi[4], Alo[4];
    {
        const float* r0 = qg + ((size_t)b * S + qbase + g) * HID + h * DH;
        const float* r1 = r0 + 8 * HID;
        const float2 qa = *reinterpret_cast<const float2*>(r0 + 2 * t);       // a0
        const float2 qc = *reinterpret_cast<const float2*>(r1 + 2 * t);       // a1
        const float2 qb2 = *reinterpret_cast<const float2*>(r0 + 2 * t + 8);  // a2
        const float2 qd = *reinterpret_cast<const float2*>(r1 + 2 * t + 8);   // a3
        float hx, lx, hy, ly;
        bf16_split(qa.x * scale, hx, lx);  bf16_split(qa.y * scale, hy, ly);
        Ahi[0] = packbf2(hx, hy);  Alo[0] = packbf2(lx, ly);
        bf16_split(qc.x * scale, hx, lx);  bf16_split(qc.y * scale, hy, ly);
        Ahi[1] = packbf2(hx, hy);  Alo[1] = packbf2(lx, ly);
        bf16_split(qb2.x * scale, hx, lx); bf16_split(qb2.y * scale, hy, ly);
        Ahi[2] = packbf2(hx, hy);  Alo[2] = packbf2(lx, ly);
        bf16_split(qd.x * scale, hx, lx);  bf16_split(qd.y * scale, hy, ly);
        Ahi[3] = packbf2(hx, hy);  Alo[3] = packbf2(lx, ly);
    }

    float m0 = -FLT_MAX, m1 = -FLT_MAX, l0 = 0.0f, l1 = 0.0f;
    float oA0 = 0, oA1 = 0, oA2 = 0, oA3 = 0;   // d 0..7
    float oB0 = 0, oB1 = 0, oB2 = 0, oB3 = 0;   // d 8..15

    const float* kbase = kv + ((size_t)b * S) * (2 * HID) + h * DH;
    const int srow = tid >> 2;
    const int sseg = tid & 3;
    // staging word targets for d-pairs (4s,4s+1) and (4s+2,4s+3)
    const int W1 = (sseg & 1) * 4 + (sseg >> 1);
    const int W2 = W1 + 2;

// 16-key chunk: 6 QK mmas (bf16x2, k16), softmax, 4 PV mmas (tf32, key-permuted
// A-frags: no shuffles; V rows indexed 2t,2t+1 to match).
#define TC_CHUNK16(K0, MASKED)                                                  \
do {                                                                            \
    const uint2 kha = *reinterpret_cast<const uint2*>(&KhiW[((K0) + g) * 8 + 2 * t]);     \
    const uint2 kla = *reinterpret_cast<const uint2*>(&KloW[((K0) + g) * 8 + 2 * t]);     \
    const uint2 khb = *reinterpret_cast<const uint2*>(&KhiW[((K0) + 8 + g) * 8 + 2 * t]); \
    const uint2 klb = *reinterpret_cast<const uint2*>(&KloW[((K0) + 8 + g) * 8 + 2 * t]); \
    float s0, s1, s2, s3, s4, s5, s6, s7;                                       \
    mma16b(s0,s1,s2,s3, Ahi[0],Ahi[1],Ahi[2],Ahi[3], kha.x,kha.y, 0.f,0.f,0.f,0.f); \
    mma16b(s4,s5,s6,s7, Ahi[0],Ahi[1],Ahi[2],Ahi[3], khb.x,khb.y, 0.f,0.f,0.f,0.f); \
    mma16b(s0,s1,s2,s3, Alo[0],Alo[1],Alo[2],Alo[3], kha.x,kha.y, s0,s1,s2,s3); \
    mma16b(s4,s5,s6,s7, Alo[0],Alo[1],Alo[2],Alo[3], khb.x,khb.y, s4,s5,s6,s7); \
    mma16b(s0,s1,s2,s3, Ahi[0],Ahi[1],Ahi[2],Ahi[3], kla.x,kla.y, s0,s1,s2,s3); \
    mma16b(s4,s5,s6,s7, Ahi[0],Ahi[1],Ahi[2],Ahi[3], klb.x,klb.y, s4,s5,s6,s7); \
    if (MASKED) {                                                               \
        bool v0 = ((K0) + 2 * t)     < tn;                                      \
        bool v1 = ((K0) + 2 * t + 1) < tn;                                      \
        bool v2 = ((K0) + 8 + 2 * t)     < tn;                                  \
        bool v3 = ((K0) + 8 + 2 * t + 1) < tn;                                  \
        s0 = v0 ? s0 : -FLT_MAX;  s1 = v1 ? s1 : -FLT_MAX;                      \
        s2 = v0 ? s2 : -FLT_MAX;  s3 = v1 ? s3 : -FLT_MAX;                      \
        s4 = v2 ? s4 : -FLT_MAX;  s5 = v3 ? s5 : -FLT_MAX;                      \
        s6 = v2 ? s6 : -FLT_MAX;  s7 = v3 ? s7 : -FLT_MAX;                      \
    }                                                                           \
    float r0 = fmaxf(fmaxf(s0, s1), fmaxf(s4, s5));   /* row g   */             \
    float r1 = fmaxf(fmaxf(s2, s3), fmaxf(s6, s7));   /* row g+8 */             \
    r0 = fmaxf(r0, __shfl_xor_sync(0xffffffffu, r0, 1));                        \
    r0 = fmaxf(r0, __shfl_xor_sync(0xffffffffu, r0, 2));                        \
    r1 = fmaxf(r1, __shfl_xor_sync(0xffffffffu, r1, 1));                        \
    r1 = fmaxf(r1, __shfl_xor_sync(0xffffffffu, r1, 2));                        \
    float mn0 = fmaxf(m0, r0), mn1 = fmaxf(m1, r1);                             \
    float co0 = fast_exp2(m0 - mn0), co1 = fast_exp2(m1 - mn1);                 \
    m0 = mn0; m1 = mn1;                                                         \
    uint32_t u0 = tf32r(fast_exp2(s0 - mn0));                                   \
    uint32_t u1 = tf32r(fast_exp2(s1 - mn0));                                   \
    uint32_t u2 = tf32r(fast_exp2(s2 - mn1));                                   \
    uint32_t u3 = tf32r(fast_exp2(s3 - mn1));                                   \
    uint32_t u4 = tf32r(fast_exp2(s4 - mn0));                                   \
    uint32_t u5 = tf32r(fast_exp2(s5 - mn0));                                   \
    uint32_t u6 = tf32r(fast_exp2(s6 - mn1));                                   \
    uint32_t u7 = tf32r(fast_exp2(s7 - mn1));                                   \
    l0 = l0 * co0 + ((__uint_as_float(u0) + __uint_as_float(u1))                \
                   + (__uint_as_float(u4) + __uint_as_float(u5)));              \
    l1 = l1 * co1 + ((__uint_as_float(u2) + __uint_as_float(u3))                \
                   + (__uint_as_float(u6) + __uint_as_float(u7)));              \
    oA0 *= co0; oA1 *= co0; oA2 *= co1; oA3 *= co1;                             \
    oB0 *= co0; oB1 *= co0; oB2 *= co1; oB3 *= co1;                             \
    /* key-permuted PV: A logical col j=t holds key 2t, j=t+4 holds key 2t+1 */ \
    const int va0 = ((K0) + 2 * t) * VSTR,     va1 = va0 + VSTR;                \
    const int vb0 = ((K0) + 8 + 2 * t) * VSTR, vb1 = vb0 + VSTR;                \
    uint32_t vA0 = __float_as_uint(Vhi[va0 + g]);                               \
    uint32_t vA1 = __float_as_uint(Vhi[va1 + g]);                               \
    uint32_t vA2 = __float_as_uint(Vhi[va0 + g + 8]);                           \
    uint32_t vA3 = __float_as_uint(Vhi[va1 + g + 8]);                           \
    uint32_t vB0 = __float_as_uint(Vhi[vb0 + g]);                               \
    uint32_t vB1 = __float_as_uint(Vhi[vb1 + g]);                               \
    uint32_t vB2 = __float_as_uint(Vhi[vb0 + g + 8]);                           \
    uint32_t vB3 = __float_as_uint(Vhi[vb1 + g + 8]);                           \
    mma8(oA0,oA1,oA2,oA3, u0,u2,u1,u3, vA0,vA1, oA0,oA1,oA2,oA3);               \
    mma8(oB0,oB1,oB2,oB3, u0,u2,u1,u3, vA2,vA3, oB0,oB1,oB2,oB3);               \
    mma8(oA0,oA1,oA2,oA3, u4,u6,u5,u7, vB0,vB1, oA0,oA1,oA2,oA3);               \
    mma8(oB0,oB1,oB2,oB3, u4,u6,u5,u7, vB2,vB3, oB0,oB1,oB2,oB3);               \
} while (0)

    for (int t0 = start; t0 < end; t0 += TK) {
        const int tn = min(TK, end - t0);

        __syncthreads();
        // ---- Stage K (bf16 hi/lo, d-pair-interleaved) and V (tf32-RNA) ----
#pragma unroll
        for (int r = 0; r < TK; r += 32) {
            const int rr = srow + r;
            float4 k4 = make_float4(0.f, 0.f, 0.f, 0.f);
            float4 v4 = make_float4(0.f, 0.f, 0.f, 0.f);
            if (rr < tn) {
                const float* src = kbase + (size_t)(t0 + rr) * (2 * HID) + sseg * 4;
                k4 = *reinterpret_cast<const float4*>(src);
                v4 = *reinterpret_cast<const float4*>(src + HID);
            }
            float hx, lx, hy, ly, hz, lz, hw, lw;
            bf16_split(k4.x, hx, lx);  bf16_split(k4.y, hy, ly);
            bf16_split(k4.z, hz, lz);  bf16_split(k4.w, hw, lw);
            KhiW[rr * 8 + W1] = packbf2(hx, hy);
            KhiW[rr * 8 + W2] = packbf2(hz, hw);
            KloW[rr * 8 + W1] = packbf2(lx, ly);
            KloW[rr * 8 + W2] = packbf2(lz, lw);
            *reinterpret_cast<float4*>(&Vhi[rr * VSTR + sseg * 4]) = make_float4(
                __uint_as_float(tf32r(v4.x)), __uint_as_float(tf32r(v4.y)),
                __uint_as_float(tf32r(v4.z)), __uint_as_float(tf32r(v4.w)));
        }
        __syncthreads();

        const int nfull = tn >> 4;
        for (int ic = 0; ic < nfull; ic++) {
            TC_CHUNK16(ic * 16, 0);
        }
        if (tn & 15) {
            TC_CHUNK16(nfull * 16, 1);
        }
    }

    // ---- Finalize: quad-reduce l (m already quad-uniform), write partials ----
    l0 += __shfl_xor_sync(0xffffffffu, l0, 1);
    l0 += __shfl_xor_sync(0xffffffffu, l0, 2);
    l1 += __shfl_xor_sync(0xffffffffu, l1, 1);
    l1 += __shfl_xor_sync(0xffffffffu, l1, 2);

    const int bh_ = b * NH + h;
    const int q0g = qbase + g;
    const int q1g = qbase + g + 8;
    if (t == 0) {
        g_m[sp * BNS + bh_ * S + q0g] = m0;
        g_l[sp * BNS + bh_ * S + q0g] = l0;
        g_m[sp * BNS + bh_ * S + q1g] = m1;
        g_l[sp * BNS + bh_ * S + q1g] = l1;
    }
    const size_t ob = (size_t)(sp * BH + bh_) * 8;
    g_o[(ob + t    ) * S + q0g] = make_float2(oA0, oA1);   // d pair (2t, 2t+1)
    g_o[(ob + t + 4) * S + q0g] = make_float2(oB0, oB1);   // d pair (8+2t, 8+2t+1)
    g_o[(ob + t    ) * S + q1g] = make_float2(oA2, oA3);
    g_o[(ob + t + 4) * S + q1g] = make_float2(oB2, oB3);
}

__global__ __launch_bounds__(256) void mha_combine_kernel(
    float* __restrict__ out, int S, int total)   // total = B*NH*S
{
    int idx = blockIdx.x * 256 + threadIdx.x;
    if (idx >= total) return;
    const int q  = idx % S;
    const int bh = idx / S;
    const int h  = bh % NH;
    const int b  = bh / NH;
    const int base = bh * S + q;

    float m[NSPLIT], l[NSPLIT];
    float mm = -FLT_MAX;
#pragma unroll
    for (int sp = 0; sp < NSPLIT; sp++) {
        m[sp] = g_m[sp * BNS + base];
        l[sp] = g_l[sp * BNS + base];
        mm = fmaxf(mm, m[sp]);
    }
    float a[NSPLIT];
    float denom = 0.0f;
#pragma unroll
    for (int sp = 0; sp < NSPLIT; sp++) {
        a[sp] = fast_exp2(m[sp] - mm);     // empty split: m=-FLT_MAX -> 0
        denom = fmaf(l[sp], a[sp], denom);
    }
    const float inv = 1.0f / denom;        // n>=1 guarantees split-0 l>0
#pragma unroll
    for (int sp = 0; sp < NSPLIT; sp++) a[sp] *= inv;

    // g_o grp holds d pair (2*grp, 2*grp+1) for grp<4, (8+2*(grp-4), ...) for grp>=4
    float* op = out + ((size_t)b * S + q) * HID + h * DH;
#pragma unroll
    for (int grp = 0; grp < 8; grp++) {
        float2 acc = make_float2(0.f, 0.f);
#pragma unroll
        for (int sp = 0; sp < NSPLIT; sp++) {
            float2 o = g_o[((size_t)(sp * BH + bh) * 8 + grp) * S + q];
            acc.x = fmaf(o.x, a[sp], acc.x);
            acc.y = fmaf(o.y, a[sp], acc.y);
        }
        const int d0 = (grp < 4) ? (2 * grp) : (8 + 2 * (grp - 4));
        *reinterpret_cast<float2*>(op + d0) = acc;
    }
}

extern "C" void kernel_launch(void* const* d_in, const int* in_sizes, int n_in,
                              void* d_out, int out_size)
{
    const float* kv = (const float*)d_in[0];   // key_and_value [B,S,256]
    const float* qg = (const float*)d_in[1];   // query         [B,S,128]
    const int*   sl = (const int*)  d_in[2];   // seq_len       [B,1]

    const int B = in_sizes[2];                 // [B,1] ints
    const int S = in_sizes[1] / (B * HID);

    dim3 grid((S / QBLK) * NSPLIT, NH, B);
    mha_tc_kernel<<<grid, TPB>>>(kv, qg, sl, S);

    const int total = B * NH * S;
    mha_combine_kernel<<<(total + 255) / 256, 256>>>((float*)d_out, S, total);
}

// round 13
// speedup vs baseline: 2.0490x; 1.0885x over previous
#include <cuda_runtime.h>
#include <cfloat>
#include <cstdint>

// Problem constants (fixed by reference: HIDDEN=128, NUM_HEADS=8)
constexpr int DH   = 16;
constexpr int NH   = 8;
constexpr int HID  = 128;
constexpr int TPB  = 128;   // 4 warps
constexpr int QW   = 16;    // queries per warp (mma M)
constexpr int QBLK = 64;    // queries per block
constexpr int TK   = 128;   // keys per smem tile
constexpr int NSPLIT = 2;   // flash split-K
constexpr int VSTR = 20;    // V smem row stride (floats): conflict-free for rows 2t,2t+1

// Dataset-fixed max shapes (B=4, S=2048) for static scratch.
constexpr int MAXB = 4;
constexpr int MAXS = 2048;
constexpr int BH   = MAXB * NH;       // 32
constexpr int BNS  = BH * MAXS;
constexpr int NQB  = MAXS / QBLK;     // 32

// Split-K partials. g_o layout: [sp][bh][grp(8 d-pairs)][q] as float2.
__device__ float  g_m[NSPLIT * BNS];
__device__ float  g_l[NSPLIT * BNS];
__device__ float2 g_o[NSPLIT * BH * 8 * MAXS];
__device__ int    g_cnt[BH * NQB];    // zero-init; winner resets -> replay-safe

__device__ __forceinline__ float fast_exp2(float x) {
    float r; asm("ex2.approx.ftz.f32 %0, %1;" : "=f"(r) : "f"(x)); return r;
}
__device__ __forceinline__ uint32_t tf32r(float x) {   // round-to-nearest tf32
    uint32_t u; asm("cvt.rna.tf32.f32 %0, %1;" : "=r"(u) : "f"(x)); return u;
}
// bf16x2 pack: low half = lo_elem, high half = hi_elem
__device__ __forceinline__ uint32_t packbf2(float lo_elem, float hi_elem) {
    uint32_t r;
    asm("cvt.rn.bf16x2.f32 %0, %1, %2;" : "=r"(r) : "f"(hi_elem), "f"(lo_elem));
    return r;
}
// RNE bf16 split: x = hf + residual (hf exactly bf16-representable)
__device__ __forceinline__ void bf16_split(float x, float& hf, float& lf) {
    uint32_t xb = __float_as_uint(x);
    uint32_t r  = (xb + 0x7FFFu + ((xb >> 16) & 1u)) & 0xFFFF0000u;
    hf = __uint_as_float(r);
    lf = x - hf;
}

// m16n8k16 bf16 mma: D = A*B + C
__device__ __forceinline__ void mma16b(
    float& d0, float& d1, float& d2, float& d3,
    uint32_t a0, uint32_t a1, uint32_t a2, uint32_t a3,
    uint32_t b0, uint32_t b1,
    float c0, float c1, float c2, float c3)
{
    asm("mma.sync.aligned.m16n8k16.row.col.f32.bf16.bf16.f32 "
        "{%0,%1,%2,%3},{%4,%5,%6,%7},{%8,%9},{%10,%11,%12,%13};"
        : "=f"(d0), "=f"(d1), "=f"(d2), "=f"(d3)
        : "r"(a0), "r"(a1), "r"(a2), "r"(a3), "r"(b0), "r"(b1),
          "f"(c0), "f"(c1), "f"(c2), "f"(c3));
}
// m16n8k8 tf32 mma: D = A*B + C
__device__ __forceinline__ void mma8(
    float& d0, float& d1, float& d2, float& d3,
    uint32_t a0, uint32_t a1, uint32_t a2, uint32_t a3,
    uint32_t b0, uint32_t b1,
    float c0, float c1, float c2, float c3)
{
    asm("mma.sync.aligned.m16n8k8.row.col.f32.tf32.tf32.f32 "
        "{%0,%1,%2,%3},{%4,%5,%6,%7},{%8,%9},{%10,%11,%12,%13};"
        : "=f"(d0), "=f"(d1), "=f"(d2), "=f"(d3)
        : "r"(a0), "r"(a1), "r"(a2), "r"(a3), "r"(b0), "r"(b1),
          "f"(c0), "f"(c1), "f"(c2), "f"(c3));
}

__global__ __launch_bounds__(TPB) void mha_tc_kernel(
    const float* __restrict__ kv,     // [B, S, 2*HID]
    const float* __restrict__ qg,     // [B, S, HID]
    const int*   __restrict__ slen,   // [B]
    float*       __restrict__ out,    // [B, S, HID]
    int S)
{
    // K rows: 8 words of bf16x2, word order (d0,1)(d8,9)(d2,3)(d10,11)(d4,5)(d12,13)(d6,7)(d14,15)
    // so thread t's B-frag {(2t,2t+1),(2t+8,2t+9)} is ONE uint2 at word 2t.
    __shared__ uint32_t KhiW[TK * 8];
    __shared__ uint32_t KloW[TK * 8];
    __shared__ float    Vhi[TK * VSTR];   // V rounded to tf32 (RNA)
    __shared__ int      s_last;

    const int tid  = threadIdx.x;
    const int warp = tid >> 5;
    const int lane = tid & 31;
    const int g    = lane >> 2;   // 0..7
    const int t    = lane & 3;    // 0..3

    const int b  = blockIdx.z;
    const int h  = blockIdx.y;
    const int qb = blockIdx.x / NSPLIT;
    const int sp = blockIdx.x % NSPLIT;
    const int n  = slen[b];

    const int chunkN = (n + NSPLIT - 1) / NSPLIT;
    const int start  = sp * chunkN;
    const int end    = min(n, start + chunkN);

    const int qbase = qb * QBLK + warp * QW;

    // ---- Q fragments (rows g, g+8; d = 2t,2t+1,2t+8,2t+9), bf16x2 hi/lo ----
    const float scale = 4.0f * 1.4426950408889634f;   // sqrt(d_head) * log2(e)
    uint32_t Ahi[4], Alo[4];
    {
        const float* r0 = qg + ((size_t)b * S + qbase + g) * HID + h * DH;
        const float* r1 = r0 + 8 * HID;
        const float2 qa = *reinterpret_cast<const float2*>(r0 + 2 * t);       // a0
        const float2 qc = *reinterpret_cast<const float2*>(r1 + 2 * t);       // a1
        const float2 qb2 = *reinterpret_cast<const float2*>(r0 + 2 * t + 8);  // a2
        const float2 qd = *reinterpret_cast<const float2*>(r1 + 2 * t + 8);   // a3
        float hx, lx, hy, ly;
        bf16_split(qa.x * scale, hx, lx);  bf16_split(qa.y * scale, hy, ly);
        Ahi[0] = packbf2(hx, hy);  Alo[0] = packbf2(lx, ly);
        bf16_split(qc.x * scale, hx, lx);  bf16_split(qc.y * scale, hy, ly);
        Ahi[1] = packbf2(hx, hy);  Alo[1] = packbf2(lx, ly);
        bf16_split(qb2.x * scale, hx, lx); bf16_split(qb2.y * scale, hy, ly);
        Ahi[2] = packbf2(hx, hy);  Alo[2] = packbf2(lx, ly);
        bf16_split(qd.x * scale, hx, lx);  bf16_split(qd.y * scale, hy, ly);
        Ahi[3] = packbf2(hx, hy);  Alo[3] = packbf2(lx, ly);
    }

    float m0 = -FLT_MAX, m1 = -FLT_MAX, l0 = 0.0f, l1 = 0.0f;
    float oA0 = 0, oA1 = 0, oA2 = 0, oA3 = 0;   // d 0..7
    float oB0 = 0, oB1 = 0, oB2 = 0, oB3 = 0;   // d 8..15

    const float* kbase = kv + ((size_t)b * S) * (2 * HID) + h * DH;
    const int srow = tid >> 2;
    const int sseg = tid & 3;
    // staging word targets for d-pairs (4s,4s+1) and (4s+2,4s+3)
    const int W1 = (sseg & 1) * 4 + (sseg >> 1);
    const int W2 = W1 + 2;

// One 8-key group of QK (3 bf16 mmas, tf32x3-equivalent precision)
#define QK_GROUP(R, S0, S1, S2, S3)                                             \
    const uint2 kh##R = *reinterpret_cast<const uint2*>(&KhiW[(krow##R) * 8 + 2 * t]); \
    const uint2 kl##R = *reinterpret_cast<const uint2*>(&KloW[(krow##R) * 8 + 2 * t]); \
    float S0, S1, S2, S3;                                                       \
    mma16b(S0,S1,S2,S3, Ahi[0],Ahi[1],Ahi[2],Ahi[3], kh##R.x,kh##R.y, 0.f,0.f,0.f,0.f); \
    mma16b(S0,S1,S2,S3, Alo[0],Alo[1],Alo[2],Alo[3], kh##R.x,kh##R.y, S0,S1,S2,S3); \
    mma16b(S0,S1,S2,S3, Ahi[0],Ahi[1],Ahi[2],Ahi[3], kl##R.x,kl##R.y, S0,S1,S2,S3);

// One 8-key PV group (keys base+2t, base+2t+1; key-permuted A frags, no shuffles)
#define PV_GROUP(BASE, U0, U1, U2, U3)                                          \
do {                                                                            \
    const int v0_ = (BASE + 2 * t) * VSTR, v1_ = v0_ + VSTR;                    \
    uint32_t w0_ = __float_as_uint(Vhi[v0_ + g]);                               \
    uint32_t w1_ = __float_as_uint(Vhi[v1_ + g]);                               \
    uint32_t w2_ = __float_as_uint(Vhi[v0_ + g + 8]);                           \
    uint32_t w3_ = __float_as_uint(Vhi[v1_ + g + 8]);                           \
    mma8(oA0,oA1,oA2,oA3, U0,U2,U1,U3, w0_,w1_, oA0,oA1,oA2,oA3);               \
    mma8(oB0,oB1,oB2,oB3, U0,U2,U1,U3, w2_,w3_, oB0,oB1,oB2,oB3);               \
} while (0)

// 32-key chunk: 12 QK mmas (4 groups), joint softmax, 8 PV mmas.
#define TC_CHUNK32(K0, MASKED)                                                  \
do {                                                                            \
    const int krowA = (K0) + g;                                                 \
    const int krowB = (K0) + 8 + g;                                             \
    const int krowC = (K0) + 16 + g;                                            \
    const int krowD = (K0) + 24 + g;                                            \
    QK_GROUP(A, sa0, sa1, sa2, sa3)                                             \
    QK_GROUP(B, sb0, sb1, sb2, sb3)                                             \
    QK_GROUP(C, sc0, sc1, sc2, sc3)                                             \
    QK_GROUP(D, sd0, sd1, sd2, sd3)                                             \
    if (MASKED) {                                                               \
        const int kk = (K0) + 2 * t;                                            \
        bool a0v = kk < tn,      a1v = kk + 1 < tn;                             \
        bool b0v = kk + 8 < tn,  b1v = kk + 9 < tn;                             \
        bool c0v = kk + 16 < tn, c1v = kk + 17 < tn;                            \
        bool d0v = kk + 24 < tn, d1v = kk + 25 < tn;                            \
        sa0 = a0v ? sa0 : -FLT_MAX;  sa1 = a1v ? sa1 : -FLT_MAX;                \
        sa2 = a0v ? sa2 : -FLT_MAX;  sa3 = a1v ? sa3 : -FLT_MAX;                \
        sb0 = b0v ? sb0 : -FLT_MAX;  sb1 = b1v ? sb1 : -FLT_MAX;                \
        sb2 = b0v ? sb2 : -FLT_MAX;  sb3 = b1v ? sb3 : -FLT_MAX;                \
        sc0 = c0v ? sc0 : -FLT_MAX;  sc1 = c1v ? sc1 : -FLT_MAX;                \
        sc2 = c0v ? sc2 : -FLT_MAX;  sc3 = c1v ? sc3 : -FLT_MAX;                \
        sd0 = d0v ? sd0 : -FLT_MAX;  sd1 = d1v ? sd1 : -FLT_MAX;                \
        sd2 = d0v ? sd2 : -FLT_MAX;  sd3 = d1v ? sd3 : -FLT_MAX;                \
    }                                                                           \
    float r0 = fmaxf(fmaxf(fmaxf(sa0, sa1), fmaxf(sb0, sb1)),                   \
                     fmaxf(fmaxf(sc0, sc1), fmaxf(sd0, sd1)));                  \
    float r1 = fmaxf(fmaxf(fmaxf(sa2, sa3), fmaxf(sb2, sb3)),                   \
                     fmaxf(fmaxf(sc2, sc3), fmaxf(sd2, sd3)));                  \
    r0 = fmaxf(r0, __shfl_xor_sync(0xffffffffu, r0, 1));                        \
    r0 = fmaxf(r0, __shfl_xor_sync(0xffffffffu, r0, 2));                        \
    r1 = fmaxf(r1, __shfl_xor_sync(0xffffffffu, r1, 1));                        \
    r1 = fmaxf(r1, __shfl_xor_sync(0xffffffffu, r1, 2));                        \
    float mn0 = fmaxf(m0, r0), mn1 = fmaxf(m1, r1);                             \
    float co0 = fast_exp2(m0 - mn0), co1 = fast_exp2(m1 - mn1);                 \
    m0 = mn0; m1 = mn1;                                                         \
    uint32_t ua0 = tf32r(fast_exp2(sa0 - mn0));                                 \
    uint32_t ua1 = tf32r(fast_exp2(sa1 - mn0));                                 \
    uint32_t ua2 = tf32r(fast_exp2(sa2 - mn1));                                 \
    uint32_t ua3 = tf32r(fast_exp2(sa3 - mn1));                                 \
    uint32_t ub0 = tf32r(fast_exp2(sb0 - mn0));                                 \
    uint32_t ub1 = tf32r(fast_exp2(sb1 - mn0));                                 \
    uint32_t ub2 = tf32r(fast_exp2(sb2 - mn1));                                 \
    uint32_t ub3 = tf32r(fast_exp2(sb3 - mn1));                                 \
    uint32_t uc0 = tf32r(fast_exp2(sc0 - mn0));                                 \
    uint32_t uc1 = tf32r(fast_exp2(sc1 - mn0));                                 \
    uint32_t uc2 = tf32r(fast_exp2(sc2 - mn1));                                 \
    uint32_t uc3 = tf32r(fast_exp2(sc3 - mn1));                                 \
    uint32_t ud0 = tf32r(fast_exp2(sd0 - mn0));                                 \
    uint32_t ud1 = tf32r(fast_exp2(sd1 - mn0));                                 \
    uint32_t ud2 = tf32r(fast_exp2(sd2 - mn1));                                 \
    uint32_t ud3 = tf32r(fast_exp2(sd3 - mn1));                                 \
    float ps0 = ((__uint_as_float(ua0) + __uint_as_float(ua1))                  \
               + (__uint_as_float(ub0) + __uint_as_float(ub1)))                 \
              + ((__uint_as_float(uc0) + __uint_as_float(uc1))                  \
               + (__uint_as_float(ud0) + __uint_as_float(ud1)));                \
    float ps1 = ((__uint_as_float(ua2) + __uint_as_float(ua3))                  \
               + (__uint_as_float(ub2) + __uint_as_float(ub3)))                 \
              + ((__uint_as_float(uc2) + __uint_as_float(uc3))                  \
               + (__uint_as_float(ud2) + __uint_as_float(ud3)));                \
    l0 = fmaf(l0, co0, ps0);                                                    \
    l1 = fmaf(l1, co1, ps1);                                                    \
    oA0 *= co0; oA1 *= co0; oA2 *= co1; oA3 *= co1;                             \
    oB0 *= co0; oB1 *= co0; oB2 *= co1; oB3 *= co1;                             \
    PV_GROUP((K0),      ua0, ua1, ua2, ua3);                                    \
    PV_GROUP((K0) + 8,  ub0, ub1, ub2, ub3);                                    \
    PV_GROUP((K0) + 16, uc0, uc1, uc2, uc3);                                    \
    PV_GROUP((K0) + 24, ud0, ud1, ud2, ud3);                                    \
} while (0)

    for (int t0 = start; t0 < end; t0 += TK) {
        const int tn = min(TK, end - t0);

        __syncthreads();
        // ---- Stage K (bf16 hi/lo, d-pair-interleaved) and V (tf32-RNA) ----
        // Invalid rows (rr >= tn) store zeros (k4/v4 defaults): masked keys see 0.
#pragma unroll
        for (int r = 0; r < TK; r += 32) {
            const int rr = srow + r;
            float4 k4 = make_float4(0.f, 0.f, 0.f, 0.f);
            float4 v4 = make_float4(0.f, 0.f, 0.f, 0.f);
            if (rr < tn) {
                const float* src = kbase + (size_t)(t0 + rr) * (2 * HID) + sseg * 4;
                k4 = *reinterpret_cast<const float4*>(src);
                v4 = *reinterpret_cast<const float4*>(src + HID);
            }
            float hx, lx, hy, ly, hz, lz, hw, lw;
            bf16_split(k4.x, hx, lx);  bf16_split(k4.y, hy, ly);
            bf16_split(k4.z, hz, lz);  bf16_split(k4.w, hw, lw);
            KhiW[rr * 8 + W1] = packbf2(hx, hy);
            KhiW[rr * 8 + W2] = packbf2(hz, hw);
            KloW[rr * 8 + W1] = packbf2(lx, ly);
            KloW[rr * 8 + W2] = packbf2(lz, lw);
            *reinterpret_cast<float4*>(&Vhi[rr * VSTR + sseg * 4]) = make_float4(
                __uint_as_float(tf32r(v4.x)), __uint_as_float(tf32r(v4.y)),
                __uint_as_float(tf32r(v4.z)), __uint_as_float(tf32r(v4.w)));
        }
        __syncthreads();

        const int nfull = tn >> 5;
        for (int ic = 0; ic < nfull; ic++) {
            TC_CHUNK32(ic * 32, 0);
        }
        if (tn & 31) {
            TC_CHUNK32(nfull * 32, 1);
        }
    }

    // ---- Finalize: quad-reduce l (m already quad-uniform) ----
    l0 += __shfl_xor_sync(0xffffffffu, l0, 1);
    l0 += __shfl_xor_sync(0xffffffffu, l0, 2);
    l1 += __shfl_xor_sync(0xffffffffu, l1, 1);
    l1 += __shfl_xor_sync(0xffffffffu, l1, 2);

    // ---- Write my split's partials ----
    const int bh_   = b * NH + h;
    const int q0g   = qbase + g;
    const int q1g   = qbase + g + 8;
    const int base0 = bh_ * S + q0g;
    const int base1 = bh_ * S + q1g;
    if (t == 0) {
        g_m[sp * BNS + base0] = m0;
        g_l[sp * BNS + base0] = l0;
        g_m[sp * BNS + base1] = m1;
        g_l[sp * BNS + base1] = l1;
    }
    const size_t ob = (size_t)(sp * BH + bh_) * 8;
    g_o[(ob + t    ) * S + q0g] = make_float2(oA0, oA1);   // d pair (2t, 2t+1)
    g_o[(ob + t + 4) * S + q0g] = make_float2(oB0, oB1);   // d pair (8+2t, 8+2t+1)
    g_o[(ob + t    ) * S + q1g] = make_float2(oA2, oA3);
    g_o[(ob + t + 4) * S + q1g] = make_float2(oB2, oB3);

    // ---- Fused combine: last-arriving split block merges and writes output ----
    __threadfence();
    __syncthreads();
    if (tid == 0) s_last = atomicAdd(&g_cnt[bh_ * NQB + qb], 1);
    __syncthreads();
    if (s_last == NSPLIT - 1) {
        __threadfence();
        const int osp = sp ^ 1;
        const size_t oob = (size_t)(osp * BH + bh_) * 8;
        const float mo0 = g_m[osp * BNS + base0];
        const float lo0 = g_l[osp * BNS + base0];
        const float mo1 = g_m[osp * BNS + base1];
        const float lo1 = g_l[osp * BNS + base1];
        const float2 xA0 = g_o[(oob + t    ) * S + q0g];
        const float2 xB0 = g_o[(oob + t + 4) * S + q0g];
        const float2 xA1 = g_o[(oob + t    ) * S + q1g];
        const float2 xB1 = g_o[(oob + t + 4) * S + q1g];
        const bool i0 = (sp == 0);   // order merge by split index: replay-deterministic

        // row 0
        {
            float mA = i0 ? m0 : mo0,  lA = i0 ? l0 : lo0;    // split 0
            float mB = i0 ? mo0 : m0,  lB = i0 ? lo0 : l0;    // split 1
            float mm = fmaxf(mA, mB);
            float a0s = fast_exp2(mA - mm), a1s = fast_exp2(mB - mm);
            float inv = 1.0f / fmaf(lA, a0s, lB * a1s);       // n>=1 -> denom > 0
            a0s *= inv; a1s *= inv;
            float2 pA = i0 ? make_float2(oA0, oA1) : xA0;
            float2 qA = i0 ? xA0 : make_float2(oA0, oA1);
            float2 pB = i0 ? make_float2(oB0, oB1) : xB0;
            float2 qB = i0 ? xB0 : make_float2(oB0, oB1);
            float* op = out + ((size_t)b * S + q0g) * HID + h * DH;
            *reinterpret_cast<float2*>(op + 2 * t) =
                make_float2(fmaf(pA.x, a0s, qA.x * a1s), fmaf(pA.y, a0s, qA.y * a1s));
            *reinterpret_cast<float2*>(op + 8 + 2 * t) =
                make_float2(fmaf(pB.x, a0s, qB.x * a1s), fmaf(pB.y, a0s, qB.y * a1s));
        }
        // row 1
        {
            float mA = i0 ? m1 : mo1,  lA = i0 ? l1 : lo1;
            float mB = i0 ? mo1 : m1,  lB = i0 ? lo1 : l1;
            float mm = fmaxf(mA, mB);
            float a0s = fast_exp2(mA - mm), a1s = fast_exp2(mB - mm);
            float inv = 1.0f / fmaf(lA, a0s, lB * a1s);
            a0s *= inv; a1s *= inv;
            float2 pA = i0 ? make_float2(oA2, oA3) : xA1;
            float2 qA = i0 ? xA1 : make_float2(oA2, oA3);
            float2 pB = i0 ? make_float2(oB2, oB3) : xB1;
            float2 qB = i0 ? xB1 : make_float2(oB2, oB3);
            float* op = out + ((size_t)b * S + q1g) * HID + h * DH;
            *reinterpret_cast<float2*>(op + 2 * t) =
                make_float2(fmaf(pA.x, a0s, qA.x * a1s), fmaf(pA.y, a0s, qA.y * a1s));
            *reinterpret_cast<float2*>(op + 8 + 2 * t) =
                make_float2(fmaf(pB.x, a0s, qB.x * a1s), fmaf(pB.y, a0s, qB.y * a1s));
        }

        if (tid == 0) g_cnt[bh_ * NQB + qb] = 0;   // reset for next graph replay
    }
}

extern "C" void kernel_launch(void* const* d_in, const int* in_sizes, int n_in,
                              void* d_out, int out_size)
{
    const float* kv = (const float*)d_in[0];   // key_and_value [B,S,256]
    const float* qg = (const float*)d_in[1];   // query         [B,S,128]
    const int*   sl = (const int*)  d_in[2];   // seq_len       [B,1]

    const int B = in_sizes[2];                 // [B,1] ints
    const int S = in_sizes[1] / (B * HID);

    dim3 grid((S / QBLK) * NSPLIT, NH, B);
    mha_tc_kernel<<<grid, TPB>>>(kv, qg, sl, (float*)d_out, S);
}